// round 1
// baseline (speedup 1.0000x reference)
#include <cuda_runtime.h>
#include <cuda_bf16.h>

// Problem constants (fixed by setup_inputs)
#define CH    16
#define HH    512
#define WW    512
#define KS    7
#define RAD   3
#define DIL   2
#define PAD   6            // RAD*DIL
#define DYN   3            // output channels

// Tiling
#define TW    32
#define TH    8
#define LW    (TW + 2*PAD)   // 44
#define LH    (TH + 2*PAD)   // 20
#define PLANE (LW*LH)        // 880
#define NTHREADS 256

#define SMEM_BYTES ((CH + 1) * PLANE * sizeof(float))   // 59840 B

__global__ __launch_bounds__(NTHREADS, 3)
void bilateral_kernel(const float* __restrict__ in,
                      const float* __restrict__ prm,
                      float* __restrict__ out)
{
    extern __shared__ float sm[];
    float* tile = sm;                    // [CH][LH][LW]
    float* s2t  = sm + CH * PLANE;       // [LH][LW], -1e30 marks invalid (OOB) pixels

    const int tx  = threadIdx.x;         // 0..31
    const int ty  = threadIdx.y;         // 0..7
    const int tid = ty * TW + tx;
    const int bx0 = blockIdx.x * TW;
    const int by0 = blockIdx.y * TH;
    const int b   = blockIdx.z;

    // Range / spatial coefficients (L1/L2 cached broadcast loads)
    float rc[CH];
    #pragma unroll
    for (int c = 0; c < CH; c++) rc[c] = __ldg(&prm[c]);
    const float sx = __ldg(&prm[CH]);
    const float sy = __ldg(&prm[CH + 1]);

    const float* inb = in + (size_t)b * CH * HH * WW;

    // ---- Phase 1: load haloed tile (zero-fill OOB) ----
    for (int idx = tid; idx < CH * PLANE; idx += NTHREADS) {
        int c  = idx / PLANE;
        int p  = idx - c * PLANE;
        int lr = p / LW;
        int lc = p - lr * LW;
        int gy = by0 + lr - PAD;
        int gx = bx0 + lc - PAD;
        float v = 0.0f;
        if ((unsigned)gy < (unsigned)HH && (unsigned)gx < (unsigned)WW)
            v = __ldg(&inb[(size_t)c * HH * WW + (size_t)gy * WW + gx]);
        tile[c * PLANE + p] = v;
    }
    __syncthreads();

    // ---- Phase 2: s2(q) = sum_c rc_c * x_c(q)^2 ; -1e30 where invalid ----
    for (int p = tid; p < PLANE; p += NTHREADS) {
        int lr = p / LW;
        int lc = p - lr * LW;
        int gy = by0 + lr - PAD;
        int gx = bx0 + lc - PAD;
        float s = -1e30f;
        if ((unsigned)gy < (unsigned)HH && (unsigned)gx < (unsigned)WW) {
            float a0 = 0.f, a1 = 0.f, a2 = 0.f, a3 = 0.f;
            #pragma unroll
            for (int c = 0; c < CH; c += 4) {
                float x0 = tile[(c + 0) * PLANE + p];
                float x1 = tile[(c + 1) * PLANE + p];
                float x2 = tile[(c + 2) * PLANE + p];
                float x3 = tile[(c + 3) * PLANE + p];
                a0 = fmaf(rc[c + 0] * x0, x0, a0);
                a1 = fmaf(rc[c + 1] * x1, x1, a1);
                a2 = fmaf(rc[c + 2] * x2, x2, a2);
                a3 = fmaf(rc[c + 3] * x3, x3, a3);
            }
            s = (a0 + a1) + (a2 + a3);
        }
        s2t[p] = s;
    }
    __syncthreads();

    // ---- Phase 3: per-pixel accumulation ----
    // logw(p,q) = s2(p) + s2(q) + sx*dx^2 + sy*dy^2 + dot(y_p, x_q),
    // with y_c(p) = -2 * rc_c * x_c(p).
    const int cp = (ty + PAD) * LW + (tx + PAD);
    float y[CH];
    #pragma unroll
    for (int c = 0; c < CH; c++)
        y[c] = -2.0f * rc[c] * tile[c * PLANE + cp];
    const float s2p = s2t[cp];

    float num0 = 0.f, num1 = 0.f, num2 = 0.f, den = 0.f;

    #pragma unroll 1
    for (int i = 0; i < KS; i++) {
        const float dyf   = (float)((i - RAD) * DIL);
        const float basei = fmaf(sy * dyf, dyf, s2p);
        const int rowoff  = (ty + i * DIL) * LW + tx;
        #pragma unroll
        for (int j = 0; j < KS; j++) {
            const int   p   = rowoff + j * DIL;
            const float dxf = (float)((j - RAD) * DIL);
            const float acc = fmaf(sx * dxf, dxf, basei) + s2t[p];

            const float xq0 = tile[0 * PLANE + p];
            const float xq1 = tile[1 * PLANE + p];
            const float xq2 = tile[2 * PLANE + p];

            float a0 = fmaf(y[0], xq0, acc);
            float a1 = y[1] * xq1;
            float a2 = y[2] * xq2;
            float a3 = y[3] * tile[3 * PLANE + p];
            #pragma unroll
            for (int c = 4; c < CH; c += 4) {
                a0 = fmaf(y[c + 0], tile[(c + 0) * PLANE + p], a0);
                a1 = fmaf(y[c + 1], tile[(c + 1) * PLANE + p], a1);
                a2 = fmaf(y[c + 2], tile[(c + 2) * PLANE + p], a2);
                a3 = fmaf(y[c + 3], tile[(c + 3) * PLANE + p], a3);
            }
            const float lw = (a0 + a1) + (a2 + a3);
            const float w  = __expf(lw);   // invalid taps: lw ~ -1e30 -> w = 0

            num0 = fmaf(w, xq0, num0);
            num1 = fmaf(w, xq1, num1);
            num2 = fmaf(w, xq2, num2);
            den += w;
        }
    }

    const float inv = __fdividef(1.0f, den);   // den >= 1 (center tap weight 1)
    const int gy = by0 + ty;
    const int gx = bx0 + tx;
    if (gy < HH && gx < WW) {
        size_t o = (size_t)b * DYN * HH * WW + (size_t)gy * WW + gx;
        out[o]                      = num0 * inv;
        out[o + (size_t)HH * WW]    = num1 * inv;
        out[o + 2 * (size_t)HH * WW] = num2 * inv;
    }
}

extern "C" void kernel_launch(void* const* d_in, const int* in_sizes, int n_in,
                              void* d_out, int out_size)
{
    const float* in  = (const float*)d_in[0];
    const float* prm = (const float*)d_in[1];
    float*       out = (float*)d_out;

    const int B = in_sizes[0] / (CH * HH * WW);   // = 4

    cudaFuncSetAttribute(bilateral_kernel,
                         cudaFuncAttributeMaxDynamicSharedMemorySize,
                         (int)SMEM_BYTES);

    dim3 block(TW, TH, 1);                        // 256 threads
    dim3 grid(WW / TW, HH / TH, B);               // 16 x 64 x 4
    bilateral_kernel<<<grid, block, SMEM_BYTES>>>(in, prm, out);
}

// round 2
// speedup vs baseline: 1.0593x; 1.0593x over previous
#include <cuda_runtime.h>
#include <cuda_bf16.h>

// Problem constants (fixed by setup_inputs)
#define CH    16
#define HH    512
#define WW    512
#define KS    7
#define RAD   3
#define DIL   2
#define PAD   6            // RAD*DIL
#define DYN   3            // output channels

// Tiling: 32 x 16 pixels per block, 256 threads, 2 pixels per thread
// Thread (tx, ty): g = ty>>1, sub = ty&1 -> local pixel rows (4g+sub, 4g+sub+2)
#define TW    32
#define TPH   16             // tile pixel height
#define LW    (TW + 2*PAD)   // 44
#define LH    (TPH + 2*PAD)  // 28
#define PLANE (LW*LH)        // 1232
#define NTHREADS 256

#define SMEM_BYTES ((CH + 1) * PLANE * sizeof(float))   // 83776 B

__global__ __launch_bounds__(NTHREADS, 2)
void bilateral_kernel(const float* __restrict__ in,
                      const float* __restrict__ prm,
                      float* __restrict__ out)
{
    extern __shared__ float sm[];
    float* tile = sm;                    // [CH][LH][LW]
    float* s2t  = sm + CH * PLANE;       // [LH][LW], -1e30 marks OOB pixels

    const int tx  = threadIdx.x;         // 0..31
    const int ty  = threadIdx.y;         // 0..7
    const int tid = ty * TW + tx;
    const int bx0 = blockIdx.x * TW;
    const int by0 = blockIdx.y * TPH;
    const int b   = blockIdx.z;

    float rc[CH];
    #pragma unroll
    for (int c = 0; c < CH; c++) rc[c] = __ldg(&prm[c]);
    const float sx = __ldg(&prm[CH]);
    const float sy = __ldg(&prm[CH + 1]);

    const float* inb = in + (size_t)b * CH * HH * WW;

    // ---- Phase 1: load haloed tile (zero-fill OOB) ----
    for (int idx = tid; idx < CH * PLANE; idx += NTHREADS) {
        int c  = idx / PLANE;
        int p  = idx - c * PLANE;
        int lr = p / LW;
        int lc = p - lr * LW;
        int gy = by0 + lr - PAD;
        int gx = bx0 + lc - PAD;
        float v = 0.0f;
        if ((unsigned)gy < (unsigned)HH && (unsigned)gx < (unsigned)WW)
            v = __ldg(&inb[(size_t)c * HH * WW + (size_t)gy * WW + gx]);
        tile[c * PLANE + p] = v;
    }
    __syncthreads();

    // ---- Phase 2: s2(q) = sum_c rc_c * x_c(q)^2 ; -1e30 where OOB ----
    for (int p = tid; p < PLANE; p += NTHREADS) {
        int lr = p / LW;
        int lc = p - lr * LW;
        int gy = by0 + lr - PAD;
        int gx = bx0 + lc - PAD;
        float s = -1e30f;
        if ((unsigned)gy < (unsigned)HH && (unsigned)gx < (unsigned)WW) {
            float a0 = 0.f, a1 = 0.f, a2 = 0.f, a3 = 0.f;
            #pragma unroll
            for (int c = 0; c < CH; c += 4) {
                float x0 = tile[(c + 0) * PLANE + p];
                float x1 = tile[(c + 1) * PLANE + p];
                float x2 = tile[(c + 2) * PLANE + p];
                float x3 = tile[(c + 3) * PLANE + p];
                a0 = fmaf(rc[c + 0] * x0, x0, a0);
                a1 = fmaf(rc[c + 1] * x1, x1, a1);
                a2 = fmaf(rc[c + 2] * x2, x2, a2);
                a3 = fmaf(rc[c + 3] * x3, x3, a3);
            }
            s = (a0 + a1) + (a2 + a3);
        }
        s2t[p] = s;
    }
    __syncthreads();

    // ---- Phase 3: two pixels per thread, rows lr0 and lr0+2 (share tap rows) ----
    const int lr0 = 4 * (ty >> 1) + (ty & 1);     // local pixel row of pixel0
    const int cp0 = (lr0 + PAD) * LW + (tx + PAD);
    const int cp1 = cp0 + 2 * LW;

    float y0[CH], y1[CH];
    #pragma unroll
    for (int c = 0; c < CH; c++) {
        y0[c] = -2.0f * rc[c] * tile[c * PLANE + cp0];
        y1[c] = -2.0f * rc[c] * tile[c * PLANE + cp1];
    }
    const float s2p0 = s2t[cp0];
    const float s2p1 = s2t[cp1];

    float sxj[KS];
    #pragma unroll
    for (int j = 0; j < KS; j++) {
        float dxf = (float)((j - RAD) * DIL);
        sxj[j] = sx * dxf * dxf;
    }

    float n00 = 0.f, n01 = 0.f, n02 = 0.f, d0 = 0.f;
    float n10 = 0.f, n11 = 0.f, n12 = 0.f, d1 = 0.f;

    // Tap rows (padded coords): lr0 + 2*i, i = 0..7.
    // i in [0,6] valid for pixel0 (dy0 = 2i-6); i in [1,7] valid for pixel1 (dy1 = 2i-8).
    #pragma unroll 1
    for (int i = 0; i < 8; i++) {
        const float dy0 = (float)(2 * i - 6);
        const float dy1 = (float)(2 * i - 8);
        float base0 = fmaf(sy * dy0, dy0, s2p0);
        float base1 = fmaf(sy * dy1, dy1, s2p1);
        if (i == 7) base0 = -3e30f;   // row invalid for pixel0 -> w=0
        if (i == 0) base1 = -3e30f;   // row invalid for pixel1 -> w=0
        const int rowoff = (lr0 + 2 * i) * LW + tx;

        #pragma unroll
        for (int j = 0; j < KS; j++) {
            const int p = rowoff + 2 * j;
            const float t = s2t[p] + sxj[j];

            float x[CH];
            #pragma unroll
            for (int c = 0; c < CH; c++) x[c] = tile[c * PLANE + p];

            float a0 = fmaf(y0[0], x[0], t + base0);
            float a1 = y0[1] * x[1];
            float a2 = y0[2] * x[2];
            float a3 = y0[3] * x[3];
            float b0 = fmaf(y1[0], x[0], t + base1);
            float b1 = y1[1] * x[1];
            float b2 = y1[2] * x[2];
            float b3 = y1[3] * x[3];
            #pragma unroll
            for (int c = 4; c < CH; c += 4) {
                a0 = fmaf(y0[c + 0], x[c + 0], a0);
                a1 = fmaf(y0[c + 1], x[c + 1], a1);
                a2 = fmaf(y0[c + 2], x[c + 2], a2);
                a3 = fmaf(y0[c + 3], x[c + 3], a3);
                b0 = fmaf(y1[c + 0], x[c + 0], b0);
                b1 = fmaf(y1[c + 1], x[c + 1], b1);
                b2 = fmaf(y1[c + 2], x[c + 2], b2);
                b3 = fmaf(y1[c + 3], x[c + 3], b3);
            }
            const float w0 = __expf((a0 + a1) + (a2 + a3));
            const float w1 = __expf((b0 + b1) + (b2 + b3));

            n00 = fmaf(w0, x[0], n00);
            n01 = fmaf(w0, x[1], n01);
            n02 = fmaf(w0, x[2], n02);
            d0 += w0;
            n10 = fmaf(w1, x[0], n10);
            n11 = fmaf(w1, x[1], n11);
            n12 = fmaf(w1, x[2], n12);
            d1 += w1;
        }
    }

    const float inv0 = __fdividef(1.0f, d0);   // den >= 1 (center tap w=1)
    const float inv1 = __fdividef(1.0f, d1);
    const int gy0 = by0 + lr0;
    const int gx  = bx0 + tx;
    size_t o0 = (size_t)b * DYN * HH * WW + (size_t)gy0 * WW + gx;
    size_t o1 = o0 + 2 * (size_t)WW;
    const size_t CS = (size_t)HH * WW;
    out[o0]          = n00 * inv0;
    out[o0 + CS]     = n01 * inv0;
    out[o0 + 2 * CS] = n02 * inv0;
    out[o1]          = n10 * inv1;
    out[o1 + CS]     = n11 * inv1;
    out[o1 + 2 * CS] = n12 * inv1;
}

extern "C" void kernel_launch(void* const* d_in, const int* in_sizes, int n_in,
                              void* d_out, int out_size)
{
    const float* in  = (const float*)d_in[0];
    const float* prm = (const float*)d_in[1];
    float*       out = (float*)d_out;

    const int B = in_sizes[0] / (CH * HH * WW);   // = 4

    cudaFuncSetAttribute(bilateral_kernel,
                         cudaFuncAttributeMaxDynamicSharedMemorySize,
                         (int)SMEM_BYTES);

    dim3 block(TW, 8, 1);                         // 256 threads
    dim3 grid(WW / TW, HH / TPH, B);              // 16 x 32 x 4
    bilateral_kernel<<<grid, block, SMEM_BYTES>>>(in, prm, out);
}

// round 3
// speedup vs baseline: 1.1577x; 1.0929x over previous
#include <cuda_runtime.h>
#include <cuda_bf16.h>

// Problem constants (fixed by setup_inputs)
#define CH    16
#define HH    512
#define WW    512
#define KS    7
#define RAD   3
#define DIL   2
#define PAD   6            // RAD*DIL
#define DYN   3            // output channels

// Tiling: 32 x 16 pixels per block, 256 threads, 2 pixels per thread
#define TW    32
#define TPH   16
#define LW    (TW + 2*PAD)   // 44
#define LH    (TPH + 2*PAD)  // 28
#define PLANE (LW*LH)        // 1232
#define NTHREADS 256
#define NPAIR (CH/2)         // 8 channel pairs

#define SMEM_BYTES ((CH + 1) * PLANE * sizeof(float))   // 83776 B

typedef unsigned long long u64;

__device__ __forceinline__ u64 pk2(float lo, float hi) {
    u64 r; asm("mov.b64 %0,{%1,%2};" : "=l"(r) : "f"(lo), "f"(hi)); return r;
}
__device__ __forceinline__ void upk2(u64 v, float& lo, float& hi) {
    asm("mov.b64 {%0,%1},%2;" : "=f"(lo), "=f"(hi) : "l"(v));
}
__device__ __forceinline__ u64 ffma2(u64 a, u64 b, u64 c) {
    u64 d; asm("fma.rn.f32x2 %0,%1,%2,%3;" : "=l"(d) : "l"(a), "l"(b), "l"(c)); return d;
}
__device__ __forceinline__ u64 fadd2(u64 a, u64 b) {
    u64 d; asm("add.rn.f32x2 %0,%1,%2;" : "=l"(d) : "l"(a), "l"(b)); return d;
}
__device__ __forceinline__ u64 fmul2(u64 a, u64 b) {
    u64 d; asm("mul.rn.f32x2 %0,%1,%2;" : "=l"(d) : "l"(a), "l"(b)); return d;
}

__global__ __launch_bounds__(NTHREADS, 2)
void bilateral_kernel(const float* __restrict__ in,
                      const float* __restrict__ prm,
                      float* __restrict__ out)
{
    extern __shared__ float sm[];
    // Channel-pair interleaved tile: u64 view [NPAIR][PLANE], pair k holds (ch 2k, 2k+1)
    u64*   tile64 = (u64*)sm;
    float* s2t    = sm + CH * PLANE;     // [LH][LW], -1e30 marks OOB pixels

    const int tx  = threadIdx.x;         // 0..31
    const int ty  = threadIdx.y;         // 0..7
    const int tid = ty * TW + tx;
    const int bx0 = blockIdx.x * TW;
    const int by0 = blockIdx.y * TPH;
    const int b   = blockIdx.z;

    float rc[CH];
    #pragma unroll
    for (int c = 0; c < CH; c++) rc[c] = __ldg(&prm[c]);
    const float sx = __ldg(&prm[CH]);
    const float sy = __ldg(&prm[CH + 1]);

    const float* inb = in + (size_t)b * CH * HH * WW;

    // ---- Phase 1: load haloed tile into pair-interleaved smem (zero-fill OOB) ----
    // idx is a direct float slot in the interleaved layout -> STS conflict-free.
    for (int idx = tid; idx < CH * PLANE; idx += NTHREADS) {
        int pair = idx / (2 * PLANE);
        int rem  = idx - pair * (2 * PLANE);
        int p    = rem >> 1;
        int c    = 2 * pair + (rem & 1);
        int lr = p / LW;
        int lc = p - lr * LW;
        int gy = by0 + lr - PAD;
        int gx = bx0 + lc - PAD;
        float v = 0.0f;
        if ((unsigned)gy < (unsigned)HH && (unsigned)gx < (unsigned)WW)
            v = __ldg(&inb[(size_t)c * HH * WW + (size_t)gy * WW + gx]);
        sm[idx] = v;
    }
    __syncthreads();

    // ---- Phase 2: s2(q) = sum_c rc_c * x_c(q)^2 ; -1e30 where OOB ----
    for (int p = tid; p < PLANE; p += NTHREADS) {
        int lr = p / LW;
        int lc = p - lr * LW;
        int gy = by0 + lr - PAD;
        int gx = bx0 + lc - PAD;
        float s = -1e30f;
        if ((unsigned)gy < (unsigned)HH && (unsigned)gx < (unsigned)WW) {
            float a0 = 0.f, a1 = 0.f, a2 = 0.f, a3 = 0.f;
            #pragma unroll
            for (int k = 0; k < NPAIR; k += 2) {
                float xl0, xh0, xl1, xh1;
                upk2(tile64[(k + 0) * PLANE + p], xl0, xh0);
                upk2(tile64[(k + 1) * PLANE + p], xl1, xh1);
                a0 = fmaf(rc[2*k + 0] * xl0, xl0, a0);
                a1 = fmaf(rc[2*k + 1] * xh0, xh0, a1);
                a2 = fmaf(rc[2*k + 2] * xl1, xl1, a2);
                a3 = fmaf(rc[2*k + 3] * xh1, xh1, a3);
            }
            s = (a0 + a1) + (a2 + a3);
        }
        s2t[p] = s;
    }
    __syncthreads();

    // ---- Phase 3: two pixels per thread (rows lr0, lr0+2 share tap rows) ----
    const int lr0 = 4 * (ty >> 1) + (ty & 1);
    const int cp0 = (lr0 + PAD) * LW + (tx + PAD);
    const int cp1 = cp0 + 2 * LW;

    // Packed y vectors: y_pair = (-2*rc) .* x_center  (per pair)
    u64 rcn2[NPAIR];
    #pragma unroll
    for (int k = 0; k < NPAIR; k++)
        rcn2[k] = pk2(-2.0f * rc[2*k], -2.0f * rc[2*k + 1]);

    u64 y0p[NPAIR], y1p[NPAIR];
    #pragma unroll
    for (int k = 0; k < NPAIR; k++) {
        y0p[k] = fmul2(rcn2[k], tile64[k * PLANE + cp0]);
        y1p[k] = fmul2(rcn2[k], tile64[k * PLANE + cp1]);
    }
    const float s2p0 = s2t[cp0];
    const float s2p1 = s2t[cp1];

    float sxj[KS];
    #pragma unroll
    for (int j = 0; j < KS; j++) {
        float dxf = (float)((j - RAD) * DIL);
        sxj[j] = sx * dxf * dxf;
    }

    float n00 = 0.f, n01 = 0.f, n02 = 0.f, d0 = 0.f;
    float n10 = 0.f, n11 = 0.f, n12 = 0.f, d1 = 0.f;

    // Tap rows (padded coords): lr0 + 2*i, i = 0..7.
    // i in [0,6] valid for pixel0 (dy0 = 2i-6); i in [1,7] valid for pixel1 (dy1 = 2i-8).
    #pragma unroll 1
    for (int i = 0; i < 8; i++) {
        const float dy0 = (float)(2 * i - 6);
        const float dy1 = (float)(2 * i - 8);
        float base0 = fmaf(sy * dy0, dy0, s2p0);
        float base1 = fmaf(sy * dy1, dy1, s2p1);
        if (i == 7) base0 = -3e30f;   // row invalid for pixel0 -> w=0
        if (i == 0) base1 = -3e30f;   // row invalid for pixel1 -> w=0
        const int rowoff = (lr0 + 2 * i) * LW + tx;

        #pragma unroll
        for (int j = 0; j < KS; j++) {
            const int p = rowoff + 2 * j;
            const float tb0 = (s2t[p] + sxj[j]) + base0;
            const float tb1 = (s2t[p] + sxj[j]) + base1;

            u64 xp[NPAIR];
            #pragma unroll
            for (int k = 0; k < NPAIR; k++) xp[k] = tile64[k * PLANE + p];

            // Pixel0 dot product: 2 packed chains of depth 4
            u64 A0 = fmul2(y0p[0], xp[0]);
            u64 A1 = fmul2(y0p[1], xp[1]);
            u64 B0 = fmul2(y1p[0], xp[0]);
            u64 B1 = fmul2(y1p[1], xp[1]);
            #pragma unroll
            for (int k = 2; k < NPAIR; k += 2) {
                A0 = ffma2(y0p[k],     xp[k],     A0);
                A1 = ffma2(y0p[k + 1], xp[k + 1], A1);
                B0 = ffma2(y1p[k],     xp[k],     B0);
                B1 = ffma2(y1p[k + 1], xp[k + 1], B1);
            }
            u64 SA = fadd2(A0, A1);
            u64 SB = fadd2(B0, B1);
            float salo, sahi, sblo, sbhi;
            upk2(SA, salo, sahi);
            upk2(SB, sblo, sbhi);

            const float w0 = __expf((salo + sahi) + tb0);
            const float w1 = __expf((sblo + sbhi) + tb1);

            float x0, x1, x2, x3dummy;
            upk2(xp[0], x0, x1);
            upk2(xp[1], x2, x3dummy);

            n00 = fmaf(w0, x0, n00);
            n01 = fmaf(w0, x1, n01);
            n02 = fmaf(w0, x2, n02);
            d0 += w0;
            n10 = fmaf(w1, x0, n10);
            n11 = fmaf(w1, x1, n11);
            n12 = fmaf(w1, x2, n12);
            d1 += w1;
        }
    }

    const float inv0 = __fdividef(1.0f, d0);   // den >= 1 (center tap w=1)
    const float inv1 = __fdividef(1.0f, d1);
    const int gy0 = by0 + lr0;
    const int gx  = bx0 + tx;
    size_t o0 = (size_t)b * DYN * HH * WW + (size_t)gy0 * WW + gx;
    size_t o1 = o0 + 2 * (size_t)WW;
    const size_t CS = (size_t)HH * WW;
    out[o0]          = n00 * inv0;
    out[o0 + CS]     = n01 * inv0;
    out[o0 + 2 * CS] = n02 * inv0;
    out[o1]          = n10 * inv1;
    out[o1 + CS]     = n11 * inv1;
    out[o1 + 2 * CS] = n12 * inv1;
}

extern "C" void kernel_launch(void* const* d_in, const int* in_sizes, int n_in,
                              void* d_out, int out_size)
{
    const float* in  = (const float*)d_in[0];
    const float* prm = (const float*)d_in[1];
    float*       out = (float*)d_out;

    const int B = in_sizes[0] / (CH * HH * WW);   // = 4

    cudaFuncSetAttribute(bilateral_kernel,
                         cudaFuncAttributeMaxDynamicSharedMemorySize,
                         (int)SMEM_BYTES);

    dim3 block(TW, 8, 1);                         // 256 threads
    dim3 grid(WW / TW, HH / TPH, B);              // 16 x 32 x 4
    bilateral_kernel<<<grid, block, SMEM_BYTES>>>(in, prm, out);
}